// round 8
// baseline (speedup 1.0000x reference)
#include <cuda_runtime.h>

// Problem constants
#define GRID_M     96
#define NUM_NODES  9216          // 96*96
#define MAX_EDGES  36864         // 4*NUM_NODES
#define IMG_W      192
#define MASK_ELEMS 84934656      // 9216*9216

// Scratch: pooled (pre-noise) values, passed K1 -> K2. No allocations allowed.
__device__ float g_pool[NUM_NODES];

// --------------------------------------------------------------------------
// K1: (a) fill entire FLOAT32 output with sentinel 9216.0f
//     (b) compute 2x2 max-pool of d_coarse into g_pool (float2-coalesced)
// Grid: 288 x 256 = 73728 threads (covers both jobs)
// --------------------------------------------------------------------------
__global__ void k_pool_fill(const float* __restrict__ dc, float* __restrict__ out) {
    int tid = blockIdx.x * blockDim.x + threadIdx.x;
    out[tid] = (float)NUM_NODES;                  // 73728 sentinels, fully coalesced
    if (tid < NUM_NODES) {
        int i = tid / GRID_M;
        int j = tid - i * GRID_M;
        const float2* r0 = reinterpret_cast<const float2*>(dc + (2 * i) * IMG_W);
        const float2* r1 = reinterpret_cast<const float2*>(dc + (2 * i + 1) * IMG_W);
        float2 a = r0[j];
        float2 b = r1[j];
        g_pool[tid] = fmaxf(fmaxf(a.x, a.y), fmaxf(b.x, b.y));
    }
}

// --------------------------------------------------------------------------
// K2: single block, 1024 threads.
//   Phase A: pool -> shared (+noise); block min/max -> threshold.
//   Phase B: thread t owns nodes [9t, 9t+9); test the <=4 diagonal neighbors
//            (|delta| <= th, then dropout_mask word != 0). 4-bit mask per node.
//            Mask is read as 32-bit words: correct for BOTH int32 {0,1} and
//            float32 {0.0f,1.0f} materializations of the JAX bool array.
//   Phase C: block exclusive scan of counts; scatter (row, col) float pairs in
//            row-major / ascending-column order == jnp.nonzero enumeration.
//            Sentinels beyond the total were pre-written by K1.
// --------------------------------------------------------------------------
__global__ __launch_bounds__(1024, 1)
void k_edges(const float* __restrict__ noise,
             const unsigned int* __restrict__ mask,
             float* __restrict__ out) {
    __shared__ float sd[NUM_NODES];
    __shared__ float smin[32], smax[32];
    __shared__ int   sws[32];
    __shared__ float sth;

    const int t    = threadIdx.x;
    const int lane = t & 31;
    const int warp = t >> 5;

    // ---- Phase A ----
    float lmin = 3.4e38f, lmax = -3.4e38f;
#pragma unroll
    for (int k = 0; k < 9; k++) {
        int l = t + k * 1024;
        float v = g_pool[l];
        lmin = fminf(lmin, v);
        lmax = fmaxf(lmax, v);
        sd[l] = v + noise[l];
    }
#pragma unroll
    for (int o = 16; o; o >>= 1) {
        lmin = fminf(lmin, __shfl_xor_sync(0xffffffffu, lmin, o));
        lmax = fmaxf(lmax, __shfl_xor_sync(0xffffffffu, lmax, o));
    }
    if (lane == 0) { smin[warp] = lmin; smax[warp] = lmax; }
    __syncthreads();
    if (t == 0) {
        float mn = smin[0], mx = smax[0];
#pragma unroll
        for (int w = 1; w < 32; w++) {
            mn = fminf(mn, smin[w]);
            mx = fmaxf(mx, smax[w]);
        }
        sth = (mx - mn) / 96.0f;   // min(M,N)=96, exact f32 op order as reference
    }
    __syncthreads();
    const float th = sth;

    // ---- Phase B ----
    unsigned mb[9];
    int      localSum = 0;
    const int base = t * 9;
#pragma unroll
    for (int k = 0; k < 9; k++) {
        int l = base + k;
        int i = l / GRID_M;
        int j = l - i * GRID_M;
        float dv = sd[l];
        unsigned rowbase = (unsigned)l * (unsigned)NUM_NODES;
        unsigned m = 0;
        // neighbors in ascending column order: (i-1,j-1) (i-1,j+1) (i+1,j-1) (i+1,j+1)
        if (i > 0  && j > 0  && fabsf(sd[l - 97] - dv) <= th && mask[rowbase + (unsigned)(l - 97)] != 0u) m |= 1u;
        if (i > 0  && j < 95 && fabsf(sd[l - 95] - dv) <= th && mask[rowbase + (unsigned)(l - 95)] != 0u) m |= 2u;
        if (i < 95 && j > 0  && fabsf(sd[l + 95] - dv) <= th && mask[rowbase + (unsigned)(l + 95)] != 0u) m |= 4u;
        if (i < 95 && j < 95 && fabsf(sd[l + 97] - dv) <= th && mask[rowbase + (unsigned)(l + 97)] != 0u) m |= 8u;
        mb[k]  = m;
        localSum += __popc(m);
    }

    // ---- Phase C: block exclusive scan ----
    int incl = localSum;
#pragma unroll
    for (int o = 1; o < 32; o <<= 1) {
        int v = __shfl_up_sync(0xffffffffu, incl, o);
        if (lane >= o) incl += v;
    }
    if (lane == 31) sws[warp] = incl;
    __syncthreads();
    if (warp == 0) {
        int v = sws[lane];     // exactly 32 warps
        int inc2 = v;
#pragma unroll
        for (int o = 1; o < 32; o <<= 1) {
            int u = __shfl_up_sync(0xffffffffu, inc2, o);
            if (lane >= o) inc2 += u;
        }
        sws[lane] = inc2 - v;  // exclusive warp prefix
    }
    __syncthreads();

    int pos = sws[warp] + (incl - localSum);
#pragma unroll
    for (int k = 0; k < 9; k++) {
        int l = base + k;
        unsigned m = mb[k];
        float fl = (float)l;
        if (m & 1u) { out[pos] = fl; out[MAX_EDGES + pos] = (float)(l - 97); pos++; }
        if (m & 2u) { out[pos] = fl; out[MAX_EDGES + pos] = (float)(l - 95); pos++; }
        if (m & 4u) { out[pos] = fl; out[MAX_EDGES + pos] = (float)(l + 95); pos++; }
        if (m & 8u) { out[pos] = fl; out[MAX_EDGES + pos] = (float)(l + 97); pos++; }
    }
}

// --------------------------------------------------------------------------
extern "C" void kernel_launch(void* const* d_in, const int* in_sizes, int n_in,
                              void* d_out, int out_size) {
    // Resolve inputs by element count (unique per input):
    //   d_coarse = 36864 (f32), noise = 9216 (f32),
    //   dropout_mask = 84934656 (bool -> materialized as 4-byte 0/1 words),
    //   R_scale = 1 (unused)
    const float*        dc    = nullptr;
    const float*        noise = nullptr;
    const unsigned int* mask  = nullptr;

    for (int i = 0; i < n_in; i++) {
        int s = in_sizes[i];
        if (s == MASK_ELEMS)      mask  = (const unsigned int*)d_in[i];
        else if (s == 36864)      dc    = (const float*)d_in[i];
        else if (s == 9216)       noise = (const float*)d_in[i];
    }

    float* out = (float*)d_out;   // [2, 36864] compared as float32

    k_pool_fill<<<288, 256>>>(dc, out);
    k_edges<<<1, 1024>>>(noise, mask, out);
}

// round 9
// speedup vs baseline: 2.1163x; 2.1163x over previous
#include <cuda_runtime.h>

// Problem constants
#define GRID_M     96
#define NUM_NODES  9216          // 96*96
#define MAX_EDGES  36864         // 4*NUM_NODES
#define IMG_W      192
#define MASK_ELEMS 84934656      // 9216*9216
#define NBLK       36            // 9216 / 256

// Scratch (no allocations allowed): all written every call before being read.
__device__ float         g_d[NUM_NODES];     // pool + noise
__device__ float         g_pmin[NBLK];
__device__ float         g_pmax[NBLK];
__device__ int           g_cnt[NBLK];        // edges per 256-node block
__device__ unsigned char g_mask[NUM_NODES];  // 4-bit neighbor mask per node

// --------------------------------------------------------------------------
// K1: sentinel-fill output, 2x2 maxpool, d = pool + noise, per-block min/max
//     partials (pre-noise pool values) for blocks 0..35.
// --------------------------------------------------------------------------
__global__ __launch_bounds__(256)
void k1_pool(const float* __restrict__ dc, const float* __restrict__ noise,
             float* __restrict__ out) {
    __shared__ float smn[8], smx[8];
    const int t   = threadIdx.x;
    const int tid = blockIdx.x * 256 + t;

    out[tid] = (float)NUM_NODES;              // 73728 sentinels, coalesced

    if (blockIdx.x < NBLK) {                  // these blocks have tid < 9216
        int i = tid / GRID_M;
        int j = tid - i * GRID_M;
        const float2* r0 = reinterpret_cast<const float2*>(dc + (2 * i) * IMG_W);
        const float2* r1 = reinterpret_cast<const float2*>(dc + (2 * i + 1) * IMG_W);
        float2 a = r0[j];
        float2 b = r1[j];
        float v = fmaxf(fmaxf(a.x, a.y), fmaxf(b.x, b.y));
        g_d[tid] = v + noise[tid];

        // block min/max of the 256 pooled values
        float mn = v, mx = v;
        const int lane = t & 31, w = t >> 5;
#pragma unroll
        for (int o = 16; o; o >>= 1) {
            mn = fminf(mn, __shfl_xor_sync(0xffffffffu, mn, o));
            mx = fmaxf(mx, __shfl_xor_sync(0xffffffffu, mx, o));
        }
        if (lane == 0) { smn[w] = mn; smx[w] = mx; }
        __syncthreads();
        if (w == 0) {
            mn = smn[lane & 7]; mx = smx[lane & 7];
#pragma unroll
            for (int o = 4; o; o >>= 1) {
                mn = fminf(mn, __shfl_xor_sync(0xffffffffu, mn, o));
                mx = fmaxf(mx, __shfl_xor_sync(0xffffffffu, mx, o));
            }
            if (lane == 0) { g_pmin[blockIdx.x] = mn; g_pmax[blockIdx.x] = mx; }
        }
    }
}

// --------------------------------------------------------------------------
// K2: 36 blocks x 256 threads, one node per thread.
//   - warp 0 reduces the 36 min/max partials -> threshold (redundant per block,
//     72 parallel L2 loads: cheaper than an extra launch)
//   - per-node: test <=4 diagonal neighbors (|delta|<=th, mask word != 0)
//   - store 4-bit mask byte + per-block edge count
// --------------------------------------------------------------------------
__global__ __launch_bounds__(256)
void k2_mask(const unsigned int* __restrict__ mask) {
    __shared__ float s_th;
    __shared__ int   sws[8];
    const int t = threadIdx.x, lane = t & 31, w = t >> 5;
    const int l = blockIdx.x * 256 + t;

    if (w == 0) {
        float mn = 3.4e38f, mx = -3.4e38f;
        if (lane < NBLK)      { mn = g_pmin[lane];            mx = g_pmax[lane]; }
        if (lane + 32 < NBLK) { mn = fminf(mn, g_pmin[lane + 32]);
                                mx = fmaxf(mx, g_pmax[lane + 32]); }
#pragma unroll
        for (int o = 16; o; o >>= 1) {
            mn = fminf(mn, __shfl_xor_sync(0xffffffffu, mn, o));
            mx = fmaxf(mx, __shfl_xor_sync(0xffffffffu, mx, o));
        }
        if (lane == 0) s_th = (mx - mn) / 96.0f;  // exact f32 order as reference
    }
    __syncthreads();
    const float th = s_th;

    const int i = l / GRID_M;
    const int j = l - i * GRID_M;
    const float dv = g_d[l];
    const unsigned rowbase = (unsigned)l * (unsigned)NUM_NODES;
    unsigned m = 0;
    // ascending-column neighbor order: (i-1,j-1) (i-1,j+1) (i+1,j-1) (i+1,j+1)
    if (i > 0  && j > 0  && fabsf(g_d[l - 97] - dv) <= th && mask[rowbase + (unsigned)(l - 97)] != 0u) m |= 1u;
    if (i > 0  && j < 95 && fabsf(g_d[l - 95] - dv) <= th && mask[rowbase + (unsigned)(l - 95)] != 0u) m |= 2u;
    if (i < 95 && j > 0  && fabsf(g_d[l + 95] - dv) <= th && mask[rowbase + (unsigned)(l + 95)] != 0u) m |= 4u;
    if (i < 95 && j < 95 && fabsf(g_d[l + 97] - dv) <= th && mask[rowbase + (unsigned)(l + 97)] != 0u) m |= 8u;

    g_mask[l] = (unsigned char)m;

    // block total edge count
    int c = __popc(m);
#pragma unroll
    for (int o = 16; o; o >>= 1) c += __shfl_xor_sync(0xffffffffu, c, o);
    if (lane == 0) sws[w] = c;
    __syncthreads();
    if (t == 0) {
        int s = 0;
#pragma unroll
        for (int k = 0; k < 8; k++) s += sws[k];
        g_cnt[blockIdx.x] = s;
    }
}

// --------------------------------------------------------------------------
// K3: 36 blocks x 256 threads. Block b computes its global base offset from
//     g_cnt[0..b), block-scans its 256 popcounts, scatters (row,col) pairs in
//     row-major / ascending-column order == jnp.nonzero enumeration.
// --------------------------------------------------------------------------
__global__ __launch_bounds__(256)
void k3_scatter(float* __restrict__ out) {
    __shared__ int s_base;
    __shared__ int sws[8];
    const int b = blockIdx.x, t = threadIdx.x, lane = t & 31, w = t >> 5;

    if (w == 0) {
        int v = (lane      < b) ? g_cnt[lane]      : 0;
        v    += (lane + 32 < b) ? g_cnt[lane + 32] : 0;
#pragma unroll
        for (int o = 16; o; o >>= 1) v += __shfl_xor_sync(0xffffffffu, v, o);
        if (lane == 0) s_base = v;
    }

    const int l = b * 256 + t;
    const unsigned m = (unsigned)g_mask[l];
    const int c = __popc(m);

    // block exclusive scan of c
    int incl = c;
#pragma unroll
    for (int o = 1; o < 32; o <<= 1) {
        int u = __shfl_up_sync(0xffffffffu, incl, o);
        if (lane >= o) incl += u;
    }
    if (lane == 31) sws[w] = incl;
    __syncthreads();
    int wbase = 0;
#pragma unroll
    for (int k = 0; k < 8; k++) wbase += (k < w) ? sws[k] : 0;

    int pos = s_base + wbase + (incl - c);
    const float fl = (float)l;
    if (m & 1u) { out[pos] = fl; out[MAX_EDGES + pos] = (float)(l - 97); pos++; }
    if (m & 2u) { out[pos] = fl; out[MAX_EDGES + pos] = (float)(l - 95); pos++; }
    if (m & 4u) { out[pos] = fl; out[MAX_EDGES + pos] = (float)(l + 95); pos++; }
    if (m & 8u) { out[pos] = fl; out[MAX_EDGES + pos] = (float)(l + 97); pos++; }
}

// --------------------------------------------------------------------------
extern "C" void kernel_launch(void* const* d_in, const int* in_sizes, int n_in,
                              void* d_out, int out_size) {
    // Resolve inputs by element count (unique per input):
    //   d_coarse = 36864 (f32), noise = 9216 (f32),
    //   dropout_mask = 84934656 (bool materialized as 4-byte 0/1 words),
    //   R_scale = 1 (unused)
    const float*        dc    = nullptr;
    const float*        noise = nullptr;
    const unsigned int* mask  = nullptr;

    for (int i = 0; i < n_in; i++) {
        int s = in_sizes[i];
        if (s == MASK_ELEMS) mask  = (const unsigned int*)d_in[i];
        else if (s == 36864) dc    = (const float*)d_in[i];
        else if (s == 9216)  noise = (const float*)d_in[i];
    }

    float* out = (float*)d_out;   // [2, 36864] compared as float32

    k1_pool   <<<288, 256>>>(dc, noise, out);
    k2_mask   <<<NBLK, 256>>>(mask);
    k3_scatter<<<NBLK, 256>>>(out);
}

// round 10
// speedup vs baseline: 2.1731x; 1.0269x over previous
#include <cuda_runtime.h>

// Problem constants
#define GRID_M     96
#define NUM_NODES  9216          // 96*96
#define MAX_EDGES  36864         // 4*NUM_NODES
#define IMG_W      192
#define MASK_ELEMS 84934656      // 9216*9216
#define NBLK       36            // 9216 / 256 blocks; all resident (<=148 SMs)

// Scratch (no allocations allowed). g_d/g_pmin/g_pmax/g_cnt are fully written
// before being read on every call. Barrier counters rotate 0->36->0 each call
// via the reset choreography below (no call-count-dependent WORK).
__device__ float g_d[NUM_NODES];     // pool + noise
__device__ float g_pmin[NBLK];
__device__ float g_pmax[NBLK];
__device__ int   g_cnt[NBLK];        // edges per 256-node block
__device__ int   g_barA;             // grid barrier counters (init 0)
__device__ int   g_barB;

// Grid-wide barrier: release (fence) -> arrive (L2 atomic) -> spin -> acquire.
// Safe because all NBLK blocks are co-resident.
__device__ __forceinline__ void grid_barrier(int* ctr) {
    __syncthreads();
    if (threadIdx.x == 0) {
        __threadfence();
        atomicAdd(ctr, 1);
        while (atomicAdd(ctr, 0) < NBLK) { }
        __threadfence();
    }
    __syncthreads();
}

// --------------------------------------------------------------------------
// Single fused kernel: 36 blocks x 256 threads, one node per thread.
// --------------------------------------------------------------------------
__global__ __launch_bounds__(256, 1)
void k_fused(const float* __restrict__ dc, const float* __restrict__ noise,
             const unsigned int* __restrict__ mask, float* __restrict__ out) {
    __shared__ float smn[8], smx[8];
    __shared__ float s_th;
    __shared__ int   sws[8];
    __shared__ int   s_base;

    const int b    = blockIdx.x;
    const int t    = threadIdx.x;
    const int lane = t & 31;
    const int w    = t >> 5;
    const int l    = b * 256 + t;          // node id, 0..9215

    // Reset barrier B (left at NBLK by the previous call). Ordered before any
    // block can arrive at barrier B: they must first pass barrier A, which
    // requires block 0's fenced arrival, which happens after this reset.
    if (b == 0 && t == 0) atomicExch(&g_barB, 0);

    // ---- Phase 0a: sentinel fill (73728 floats = 2 x float4 per thread) ----
    {
        float4 s4 = make_float4((float)NUM_NODES, (float)NUM_NODES,
                                (float)NUM_NODES, (float)NUM_NODES);
        float4* o4 = reinterpret_cast<float4*>(out);
        o4[l]             = s4;
        o4[l + NUM_NODES] = s4;
    }

    // ---- Phase 0b: 2x2 maxpool + noise; block min/max partials ----
    const int i = l / GRID_M;
    const int j = l - i * GRID_M;
    float v;
    {
        const float2* r0 = reinterpret_cast<const float2*>(dc + (2 * i) * IMG_W);
        const float2* r1 = reinterpret_cast<const float2*>(dc + (2 * i + 1) * IMG_W);
        float2 a = r0[j];
        float2 c = r1[j];
        v = fmaxf(fmaxf(a.x, a.y), fmaxf(c.x, c.y));
    }
    const float dv = v + noise[l];
    g_d[l] = dv;

    {
        float mn = v, mx = v;
#pragma unroll
        for (int o = 16; o; o >>= 1) {
            mn = fminf(mn, __shfl_xor_sync(0xffffffffu, mn, o));
            mx = fmaxf(mx, __shfl_xor_sync(0xffffffffu, mx, o));
        }
        if (lane == 0) { smn[w] = mn; smx[w] = mx; }
        __syncthreads();
        if (w == 0) {
            mn = smn[lane & 7]; mx = smx[lane & 7];
#pragma unroll
            for (int o = 4; o; o >>= 1) {
                mn = fminf(mn, __shfl_xor_sync(0xffffffffu, mn, o));
                mx = fmaxf(mx, __shfl_xor_sync(0xffffffffu, mx, o));
            }
            if (lane == 0) { g_pmin[b] = mn; g_pmax[b] = mx; }
        }
    }

    grid_barrier(&g_barA);   // publishes g_d + min/max partials chip-wide

    // ---- Phase 1: threshold (redundant per block), neighbor mask, counts ----
    if (w == 0) {
        float mn = 3.4e38f, mx = -3.4e38f;
        if (lane < NBLK)      { mn = __ldcg(&g_pmin[lane]);
                                mx = __ldcg(&g_pmax[lane]); }
        if (lane + 32 < NBLK) { mn = fminf(mn, __ldcg(&g_pmin[lane + 32]));
                                mx = fmaxf(mx, __ldcg(&g_pmax[lane + 32])); }
#pragma unroll
        for (int o = 16; o; o >>= 1) {
            mn = fminf(mn, __shfl_xor_sync(0xffffffffu, mn, o));
            mx = fmaxf(mx, __shfl_xor_sync(0xffffffffu, mx, o));
        }
        if (lane == 0) s_th = (mx - mn) / 96.0f;  // exact f32 order as reference
    }
    __syncthreads();
    const float th = s_th;

    const unsigned rowbase = (unsigned)l * (unsigned)NUM_NODES;
    unsigned m = 0;
    // ascending-column neighbor order: (i-1,j-1) (i-1,j+1) (i+1,j-1) (i+1,j+1)
    if (i > 0  && j > 0  && fabsf(__ldcg(&g_d[l - 97]) - dv) <= th && mask[rowbase + (unsigned)(l - 97)] != 0u) m |= 1u;
    if (i > 0  && j < 95 && fabsf(__ldcg(&g_d[l - 95]) - dv) <= th && mask[rowbase + (unsigned)(l - 95)] != 0u) m |= 2u;
    if (i < 95 && j > 0  && fabsf(__ldcg(&g_d[l + 95]) - dv) <= th && mask[rowbase + (unsigned)(l + 95)] != 0u) m |= 4u;
    if (i < 95 && j < 95 && fabsf(__ldcg(&g_d[l + 97]) - dv) <= th && mask[rowbase + (unsigned)(l + 97)] != 0u) m |= 8u;

    // block exclusive scan of per-thread edge counts + block total
    const int c = __popc(m);
    int incl = c;
#pragma unroll
    for (int o = 1; o < 32; o <<= 1) {
        int u = __shfl_up_sync(0xffffffffu, incl, o);
        if (lane >= o) incl += u;
    }
    if (lane == 31) sws[w] = incl;
    __syncthreads();
    int wbase = 0, total = 0;
#pragma unroll
    for (int k = 0; k < 8; k++) {
        int sv = sws[k];
        wbase += (k < w) ? sv : 0;
        total += sv;
    }
    if (t == 0) g_cnt[b] = total;
    const int excl = wbase + (incl - c);

    grid_barrier(&g_barB);   // publishes g_cnt chip-wide

    // ---- Phase 2: global base offset + scatter (jnp.nonzero order) ----
    if (w == 0) {
        int s = (lane < b) ? __ldcg(&g_cnt[lane]) : 0;
        s    += (lane + 32 < b) ? __ldcg(&g_cnt[lane + 32]) : 0;
#pragma unroll
        for (int o = 16; o; o >>= 1) s += __shfl_xor_sync(0xffffffffu, s, o);
        if (lane == 0) s_base = s;
    }
    __syncthreads();

    int pos = s_base + excl;
    const float fl = (float)l;
    if (m & 1u) { out[pos] = fl; out[MAX_EDGES + pos] = (float)(l - 97); pos++; }
    if (m & 2u) { out[pos] = fl; out[MAX_EDGES + pos] = (float)(l - 95); pos++; }
    if (m & 4u) { out[pos] = fl; out[MAX_EDGES + pos] = (float)(l + 95); pos++; }
    if (m & 8u) { out[pos] = fl; out[MAX_EDGES + pos] = (float)(l + 97); pos++; }

    // Reset barrier A for the next call. Safe: all blocks have passed barrier
    // A (implied by barrier B completing), and nobody reads A again this call.
    if (b == 0 && t == 0) atomicExch(&g_barA, 0);
}

// --------------------------------------------------------------------------
extern "C" void kernel_launch(void* const* d_in, const int* in_sizes, int n_in,
                              void* d_out, int out_size) {
    // Resolve inputs by element count (unique per input):
    //   d_coarse = 36864 (f32), noise = 9216 (f32),
    //   dropout_mask = 84934656 (bool materialized as 4-byte 0/1 words),
    //   R_scale = 1 (unused)
    const float*        dc    = nullptr;
    const float*        noise = nullptr;
    const unsigned int* mask  = nullptr;

    for (int i = 0; i < n_in; i++) {
        int s = in_sizes[i];
        if (s == MASK_ELEMS) mask  = (const unsigned int*)d_in[i];
        else if (s == 36864) dc    = (const float*)d_in[i];
        else if (s == 9216)  noise = (const float*)d_in[i];
    }

    float* out = (float*)d_out;   // [2, 36864] compared as float32

    k_fused<<<NBLK, 256>>>(dc, noise, mask, out);
}